// round 2
// baseline (speedup 1.0000x reference)
#include <cuda_runtime.h>
#include <cuda_bf16.h>
#include <math.h>

// ---------------- Problem constants ----------------
#define TT   4096
#define DD   128
#define HH   512
#define EE   256
#define WN   4
#define H3   1536

// Sequential kernel config
#define NB   128          // persistent blocks (<=148 SMs -> co-resident in wave 1)
#define NTH  512          // threads per block
#define HB   4            // hidden dims owned per block (NB*HB = 512)

// ---------------- Device scratch (static: runtime allocation forbidden) ----------------
__device__ float g_pre_x[TT * H3];          // x@W + b
__device__ float g_pre_a[TT * HH];          // x@Wa + ba
__device__ float g_pre_w[TT * WN * H3];     // emb[wid]@Ww + bw (active rows only)
__device__ float g_Ut [H3 * HH];            // U^T  : [col][k]
__device__ float g_Uwt[H3 * HH];            // Uw^T : [col][k]
__device__ float g_Uat[HH * HH];            // Ua^T : [col][k]
__device__ float g_cw[WN * HH];             // per-step word cell states
__device__ unsigned int g_ctr;              // grid barrier counter (reset per launch)
__device__ int g_nact;                      // number of active (t,w) rows
__device__ int g_act[TT * WN];              // compacted active row indices
__device__ int g_mask_mode;                 // 0=u8, 1=i32, 2=f32

// ---------------- Helpers ----------------
__device__ __forceinline__ float sigm(float x) { return 1.0f / (1.0f + expf(-x)); }

__device__ __forceinline__ bool mask_at(const void* p, int r) {
    int m = g_mask_mode;
    if (m == 1) return ((const int*)p)[r] != 0;
    if (m == 2) return ((const unsigned int*)p)[r] != 0u;
    return ((const unsigned char*)p)[r] != 0;
}

// ---------------- Init: reset counters + detect mask dtype ----------------
// First 4096 32-bit words of the mask buffer are safe under all 3 layouts
// (u8: exactly 16384 bytes; i32/f32: first 4096 of 16384 elements).
__global__ void k_init(const unsigned int* mask_words) {
    __shared__ int badI, badF;
    if (threadIdx.x == 0) { badI = 0; badF = 0; g_ctr = 0u; g_nact = 0; }
    __syncthreads();
    for (int i = threadIdx.x; i < 4096; i += blockDim.x) {
        unsigned int w = mask_words[i];
        if (w != 0u && w != 1u) badI = 1;
        if (w != 0u && w != 0x3F800000u) badF = 1;
    }
    __syncthreads();
    if (threadIdx.x == 0) g_mask_mode = (badI == 0) ? 1 : ((badF == 0) ? 2 : 0);
}

// ---------------- Compact active (t,w) rows ----------------
__global__ void k_compact(const void* wmask) {
    int r = blockIdx.x * blockDim.x + threadIdx.x;
    if (r < TT * WN && mask_at(wmask, r)) {
        int s = atomicAdd(&g_nact, 1);
        g_act[s] = r;
    }
}

// ---------------- Transpose: in[R][C] -> out[C][R] ----------------
__global__ void k_transpose(const float* __restrict__ in, float* __restrict__ out,
                            int R, int C) {
    __shared__ float tile[32][33];
    int c0 = blockIdx.x * 32, r0 = blockIdx.y * 32;
    int x = threadIdx.x, y = threadIdx.y;
    #pragma unroll
    for (int i = 0; i < 32; i += 8) tile[y + i][x] = in[(size_t)(r0 + y + i) * C + c0 + x];
    __syncthreads();
    #pragma unroll
    for (int i = 0; i < 32; i += 8) out[(size_t)(c0 + y + i) * R + r0 + x] = tile[x][y + i];
}

// ---------------- GEMM: C[M,N] = A[M,K] @ B[K,N] + bias ----------------
// 64x64 tile, BK=32, 256 threads, 4x4 microtile. M,N,K multiples as used.
__global__ void k_gemm(const float* __restrict__ A, const float* __restrict__ B,
                       const float* __restrict__ bias, float* __restrict__ C,
                       int M, int N, int K) {
    __shared__ float As[64][33];
    __shared__ float Bs[32][64];
    int mt = blockIdx.y * 64, nt = blockIdx.x * 64;
    int tid = threadIdx.x;
    int tx = tid % 16, ty = tid / 16;
    float acc[4][4] = {};
    for (int k0 = 0; k0 < K; k0 += 32) {
        #pragma unroll
        for (int p = 0; p < 8; p++) {
            int row = (tid >> 5) + p * 8, kk = tid & 31;
            As[row][kk] = A[(size_t)(mt + row) * K + k0 + kk];
        }
        #pragma unroll
        for (int p = 0; p < 8; p++) {
            int kk = (tid >> 6) + p * 4, nn = tid & 63;
            Bs[kk][nn] = B[(size_t)(k0 + kk) * N + nt + nn];
        }
        __syncthreads();
        #pragma unroll
        for (int kk = 0; kk < 32; kk++) {
            float a0 = As[ty * 4 + 0][kk], a1 = As[ty * 4 + 1][kk];
            float a2 = As[ty * 4 + 2][kk], a3 = As[ty * 4 + 3][kk];
            float4 b4 = *(const float4*)&Bs[kk][tx * 4];
            acc[0][0] += a0 * b4.x; acc[0][1] += a0 * b4.y; acc[0][2] += a0 * b4.z; acc[0][3] += a0 * b4.w;
            acc[1][0] += a1 * b4.x; acc[1][1] += a1 * b4.y; acc[1][2] += a1 * b4.z; acc[1][3] += a1 * b4.w;
            acc[2][0] += a2 * b4.x; acc[2][1] += a2 * b4.y; acc[2][2] += a2 * b4.z; acc[2][3] += a2 * b4.w;
            acc[3][0] += a3 * b4.x; acc[3][1] += a3 * b4.y; acc[3][2] += a3 * b4.z; acc[3][3] += a3 * b4.w;
        }
        __syncthreads();
    }
    #pragma unroll
    for (int i = 0; i < 4; i++) {
        int row = mt + ty * 4 + i;
        #pragma unroll
        for (int j = 0; j < 4; j++) {
            int col = nt + tx * 4 + j;
            C[(size_t)row * N + col] = acc[i][j] + bias[col];
        }
    }
}

// ---------------- Gathered GEMM: pre_w rows for active (t,w) only ----------------
__global__ void k_gemm_gather(const float* __restrict__ emb, const int* __restrict__ word_ids,
                              const float* __restrict__ B, const float* __restrict__ bias,
                              float* __restrict__ C, int N, int K) {
    int nact = g_nact;
    int mt = blockIdx.y * 64;
    if (mt >= nact) return;
    __shared__ int sR[64];
    __shared__ int sWid[64];
    __shared__ float As[64][33];
    __shared__ float Bs[32][64];
    int tid = threadIdx.x;
    if (tid < 64) {
        int ci = mt + tid;
        int r = (ci < nact) ? g_act[ci] : -1;
        sR[tid] = r;
        sWid[tid] = (r >= 0) ? word_ids[r] : 0;
    }
    __syncthreads();
    int tx = tid % 16, ty = tid / 16;
    int nt = blockIdx.x * 64;
    float acc[4][4] = {};
    for (int k0 = 0; k0 < K; k0 += 32) {
        #pragma unroll
        for (int p = 0; p < 8; p++) {
            int row = (tid >> 5) + p * 8, kk = tid & 31;
            As[row][kk] = emb[(size_t)sWid[row] * K + k0 + kk];
        }
        #pragma unroll
        for (int p = 0; p < 8; p++) {
            int kk = (tid >> 6) + p * 4, nn = tid & 63;
            Bs[kk][nn] = B[(size_t)(k0 + kk) * N + nt + nn];
        }
        __syncthreads();
        #pragma unroll
        for (int kk = 0; kk < 32; kk++) {
            float a0 = As[ty * 4 + 0][kk], a1 = As[ty * 4 + 1][kk];
            float a2 = As[ty * 4 + 2][kk], a3 = As[ty * 4 + 3][kk];
            float4 b4 = *(const float4*)&Bs[kk][tx * 4];
            acc[0][0] += a0 * b4.x; acc[0][1] += a0 * b4.y; acc[0][2] += a0 * b4.z; acc[0][3] += a0 * b4.w;
            acc[1][0] += a1 * b4.x; acc[1][1] += a1 * b4.y; acc[1][2] += a1 * b4.z; acc[1][3] += a1 * b4.w;
            acc[2][0] += a2 * b4.x; acc[2][1] += a2 * b4.y; acc[2][2] += a2 * b4.z; acc[2][3] += a2 * b4.w;
            acc[3][0] += a3 * b4.x; acc[3][1] += a3 * b4.y; acc[3][2] += a3 * b4.z; acc[3][3] += a3 * b4.w;
        }
        __syncthreads();
    }
    #pragma unroll
    for (int i = 0; i < 4; i++) {
        int r = sR[ty * 4 + i];
        if (r >= 0) {
            #pragma unroll
            for (int j = 0; j < 4; j++) {
                int col = nt + tx * 4 + j;
                C[(size_t)r * N + col] = acc[i][j] + bias[col];
            }
        }
    }
}

// ---------------- Sequential lattice scan (persistent, grid-barriered) ----------------
__global__ void __launch_bounds__(NTH, 1)
k_lattice_seq(const float* __restrict__ h0, const float* __restrict__ c0,
              const int* __restrict__ wstarts, const void* __restrict__ wmask,
              float* __restrict__ out) {
    int tid = threadIdx.x;
    int wid = tid >> 5, lane = tid & 31;
    int hbase = blockIdx.x * HB;

    __shared__ float4 sVec4[1 + WN][HH / 4];  // [0]=h_prev ; [1..WN]=h_s (A) / c_w (B)
    __shared__ float sDot[64];
    __shared__ float sPreX[3][HB], sPreA[HB];
    __shared__ float sPreW[WN][3][HB], sCS[WN][HB];
    __shared__ float sIG[HB], sOG[HB], sGG[HB], sCprev[HB];
    __shared__ int sAct[WN], sStart[WN], sNact;

    if (tid < HB) sCprev[tid] = c0[hbase + tid];

    unsigned int pno = 0;

    for (int t = 0; t < TT; t++) {
        // ---- step metadata ----
        if (tid == 0) {
            int n = 0;
            #pragma unroll
            for (int w = 0; w < WN; w++) {
                int r = t * WN + w;
                if (mask_at(wmask, r)) { sAct[n] = w; sStart[n] = wstarts[r]; n++; }
            }
            sNact = n;
        }
        __syncthreads();
        int nact = sNact;

        // ---- stage vectors + scalars ----
        {
            int nv = 1 + nact;
            const float4* src0 = (t == 0) ? (const float4*)h0
                                          : (const float4*)(out + (size_t)(t - 1) * (2 * HH));
            for (int i = tid; i < nv * 128; i += NTH) {
                int v = i >> 7, j = i & 127;
                const float4* s = (v == 0) ? src0
                                           : (const float4*)(out + (size_t)sStart[v - 1] * (2 * HH));
                sVec4[v][j] = __ldcg(s + j);
            }
            if (tid < 3 * HB) {                       // tid 0..11
                int m = tid / HB, hh = tid % HB;
                sPreX[m][hh] = g_pre_x[(size_t)t * H3 + m * HH + hbase + hh];
            } else if (tid >= 32 && tid < 32 + HB) {  // tid 32..35
                sPreA[tid - 32] = g_pre_a[(size_t)t * HH + hbase + (tid - 32)];
            }
            int q = tid - 64;                         // tid 64..111
            if (q >= 0 && q < nact * 3 * HB) {
                int a = q / (3 * HB), s2 = q % (3 * HB), m = s2 / HB, hh = s2 % HB;
                int r = t * WN + sAct[a];
                sPreW[a][m][hh] = g_pre_w[(size_t)r * H3 + m * HH + hbase + hh];
            }
            int q2 = tid - 128;                       // tid 128..143
            if (q2 >= 0 && q2 < nact * HB) {
                int a = q2 / HB, hh = q2 % HB;
                sCS[a][hh] = __ldcg(out + (size_t)sStart[a] * (2 * HH) + HH + hbase + hh);
            }
        }
        __syncthreads();

        // ---- Phase A dots: h_prev@U cols (i,o,g) + h_s@Uw cols (f,i,g) ----
        int ndots = 3 * HB * (1 + nact);
        for (int d = wid; d < ndots; d += NTH / 32) {
            int grp = d / (3 * HB), s2 = d % (3 * HB), m = s2 / HB, hh = s2 % HB;
            const float4* vec = sVec4[grp];
            const float* wt = (grp == 0) ? g_Ut : g_Uwt;
            const float4* col = (const float4*)(wt + (size_t)(m * HH + hbase + hh) * HH);
            float acc = 0.f;
            #pragma unroll
            for (int i = 0; i < 4; i++) {
                float4 v = vec[lane + 32 * i];
                float4 c = __ldg(col + lane + 32 * i);
                acc += v.x * c.x + v.y * c.y + v.z * c.z + v.w * c.w;
            }
            #pragma unroll
            for (int o = 16; o; o >>= 1) acc += __shfl_down_sync(0xffffffffu, acc, o);
            if (lane == 0) sDot[d] = acc;
        }
        __syncthreads();

        // ---- Phase A pointwise ----
        if (tid < HB) {
            int hh = tid;
            sIG[hh] = sigm(sPreX[0][hh] + sDot[0 * HB + hh]);
            sOG[hh] = sigm(sPreX[1][hh] + sDot[1 * HB + hh]);
            sGG[hh] = tanhf(sPreX[2][hh] + sDot[2 * HB + hh]);
        }
        int q3 = tid - 32;
        if (q3 >= 0 && q3 < nact * HB) {
            int a = q3 / HB, hh = q3 % HB;
            int base = (1 + a) * 3 * HB;
            float f  = sPreW[a][0][hh] + sDot[base + 0 * HB + hh];
            float iw = sPreW[a][1][hh] + sDot[base + 1 * HB + hh];
            float gw = sPreW[a][2][hh] + sDot[base + 2 * HB + hh];
            float cw = sigm(f) * sCS[a][hh] + sigm(iw) * tanhf(gw);
            __stcg(&g_cw[sAct[a] * HH + hbase + hh], cw);
        }

        if (nact > 0) {
            // ---- grid barrier 1 (publish c_w) ----
            __threadfence();
            __syncthreads();
            pno++;
            if (tid == 0) {
                atomicAdd(&g_ctr, 1u);
                unsigned int tgt = pno * NB;
                while (*((volatile unsigned int*)&g_ctr) < tgt) {}
                __threadfence();
            }
            __syncthreads();

            // ---- Phase B stage: full c_w vectors ----
            for (int i = tid; i < nact * 128; i += NTH) {
                int a = i >> 7, j = i & 127;
                sVec4[1 + a][j] = __ldcg((const float4*)(g_cw + sAct[a] * HH) + j);
            }
            __syncthreads();

            // ---- Phase B dots: c_w @ Ua cols ----
            for (int d = wid; d < nact * HB; d += NTH / 32) {
                int a = d / HB, hh = d % HB;
                const float4* vec = sVec4[1 + a];
                const float4* col = (const float4*)(g_Uat + (size_t)(hbase + hh) * HH);
                float acc = 0.f;
                #pragma unroll
                for (int i = 0; i < 4; i++) {
                    float4 v = vec[lane + 32 * i];
                    float4 c = __ldg(col + lane + 32 * i);
                    acc += v.x * c.x + v.y * c.y + v.z * c.z + v.w * c.w;
                }
                #pragma unroll
                for (int o = 16; o; o >>= 1) acc += __shfl_down_sync(0xffffffffu, acc, o);
                if (lane == 0) sDot[d] = acc;
            }
            __syncthreads();
        } else {
            __syncthreads();
        }

        // ---- Phase B pointwise: softmax combine + write h,c ----
        if (tid < HB) {
            int hh = tid;
            float c1;
            if (nact > 0) {
                float e0 = expf(sIG[hh]);
                float num = e0 * sGG[hh], den = e0;
                for (int a = 0; a < nact; a++) {
                    float al = sigm(sPreA[hh] + sDot[a * HB + hh]);
                    float ea = expf(al);
                    float cwv = ((const float*)sVec4[1 + a])[hbase + hh];
                    num += ea * cwv;
                    den += ea;
                }
                c1 = num / den;
            } else {
                c1 = (1.0f - sIG[hh]) * sCprev[hh] + sIG[hh] * sGG[hh];
            }
            float h1 = sOG[hh] * tanhf(c1);
            __stcg(out + (size_t)t * (2 * HH) + hbase + hh, h1);
            __stcg(out + (size_t)t * (2 * HH) + HH + hbase + hh, c1);
            sCprev[hh] = c1;
        }
        // ---- grid barrier 2 (publish h1,c1) ----
        __threadfence();
        __syncthreads();
        pno++;
        if (tid == 0) {
            atomicAdd(&g_ctr, 1u);
            unsigned int tgt = pno * NB;
            while (*((volatile unsigned int*)&g_ctr) < tgt) {}
            __threadfence();
        }
        __syncthreads();
    }
}

// ---------------- Launch ----------------
extern "C" void kernel_launch(void* const* d_in, const int* in_sizes, int n_in,
                              void* d_out, int out_size) {
    const float* x       = (const float*)d_in[0];
    const int*   wids    = (const int*)d_in[1];
    const int*   wstarts = (const int*)d_in[2];
    const void*  wmask   = (const void*)d_in[3];
    const float* h0      = (const float*)d_in[4];
    const float* c0      = (const float*)d_in[5];
    const float* emb     = (const float*)d_in[6];
    const float* W       = (const float*)d_in[7];
    const float* U       = (const float*)d_in[8];
    const float* b       = (const float*)d_in[9];
    const float* Wa      = (const float*)d_in[10];
    const float* Ua      = (const float*)d_in[11];
    const float* ba      = (const float*)d_in[12];
    const float* Ww      = (const float*)d_in[13];
    const float* Uw      = (const float*)d_in[14];
    const float* bw      = (const float*)d_in[15];
    float* out = (float*)d_out;

    float *pre_x_p, *pre_a_p, *pre_w_p, *Ut_p, *Uwt_p, *Uat_p;
    cudaGetSymbolAddress((void**)&pre_x_p, g_pre_x);
    cudaGetSymbolAddress((void**)&pre_a_p, g_pre_a);
    cudaGetSymbolAddress((void**)&pre_w_p, g_pre_w);
    cudaGetSymbolAddress((void**)&Ut_p,  g_Ut);
    cudaGetSymbolAddress((void**)&Uwt_p, g_Uwt);
    cudaGetSymbolAddress((void**)&Uat_p, g_Uat);

    // 1. reset + mask dtype detection
    k_init<<<1, 256>>>((const unsigned int*)wmask);
    // 2. compact active (t,w) rows
    k_compact<<<(TT * WN + 255) / 256, 256>>>(wmask);
    // 3. weight transposes (column-major for the scan's column dots)
    k_transpose<<<dim3(H3 / 32, HH / 32), dim3(32, 8)>>>(U,  Ut_p,  HH, H3);
    k_transpose<<<dim3(H3 / 32, HH / 32), dim3(32, 8)>>>(Uw, Uwt_p, HH, H3);
    k_transpose<<<dim3(HH / 32, HH / 32), dim3(32, 8)>>>(Ua, Uat_p, HH, HH);
    // 4. dense precompute GEMMs
    k_gemm<<<dim3(H3 / 64, TT / 64), 256>>>(x, W,  b,  pre_x_p, TT, H3, DD);
    k_gemm<<<dim3(HH / 64, TT / 64), 256>>>(x, Wa, ba, pre_a_p, TT, HH, DD);
    // 5. gathered word-embedding GEMM (active rows only; blocks self-trim on g_nact)
    k_gemm_gather<<<dim3(H3 / 64, (TT * WN) / 64), 256>>>(emb, wids, Ww, bw, pre_w_p, H3, EE);
    // 6. sequential lattice scan
    k_lattice_seq<<<NB, NTH>>>(h0, c0, wstarts, wmask, out);
}

// round 4
// speedup vs baseline: 1.1599x; 1.1599x over previous
#include <cuda_runtime.h>
#include <cuda_bf16.h>
#include <math.h>

// ---------------- Problem constants ----------------
#define TT   4096
#define DD   128
#define HH   512
#define EE   256
#define WN   4
#define H3   1536

// Sequential kernel config
#define NB   64           // persistent blocks (co-resident wave 1)
#define NTH  512          // threads per block
#define HB   8            // hidden dims owned per block (NB*HB = 512)
#define NW   (NTH/32)     // 16 warps

// ---------------- Device scratch ----------------
__device__ float g_pre_x[TT * H3];
__device__ float g_pre_a[TT * HH];
__device__ float g_pre_w[TT * WN * H3];
__device__ float g_Ut [H3 * HH];            // U^T  [col][k]
__device__ float g_Uwt[H3 * HH];            // Uw^T [col][k]
__device__ float g_Uat[HH * HH];            // Ua^T [col][k]
__device__ float g_cw[WN * HH];
__device__ unsigned int g_ctr;
__device__ int g_nact;
__device__ int g_act[TT * WN];
__device__ int g_mask_mode;

// ---------------- Helpers ----------------
__device__ __forceinline__ float sigm(float x) { return 1.0f / (1.0f + __expf(-x)); }
__device__ __forceinline__ float tanh_fast(float x) {
    return 1.0f - 2.0f / (__expf(2.0f * x) + 1.0f);
}

__device__ __forceinline__ bool mask_at(const void* p, int r) {
    int m = g_mask_mode;
    if (m == 1) return ((const int*)p)[r] != 0;
    if (m == 2) return ((const unsigned int*)p)[r] != 0u;
    return ((const unsigned char*)p)[r] != 0;
}

__device__ __forceinline__ void arrive_release(unsigned int* p) {
    asm volatile("red.release.gpu.global.add.u32 [%0], 1;" :: "l"(p) : "memory");
}
__device__ __forceinline__ unsigned int ld_acq(const unsigned int* p) {
    unsigned int v;
    asm volatile("ld.acquire.gpu.global.u32 %0, [%1];" : "=r"(v) : "l"(p) : "memory");
    return v;
}

// ---------------- (0) Init: reset counters + detect mask dtype ----------------
__global__ void k_init(const unsigned int* mask_words) {
    __shared__ int badI, badF;
    if (threadIdx.x == 0) { badI = 0; badF = 0; g_ctr = 0u; g_nact = 0; }
    __syncthreads();
    for (int i = threadIdx.x; i < 4096; i += blockDim.x) {
        unsigned int w = mask_words[i];
        if (w != 0u && w != 1u) badI = 1;
        if (w != 0u && w != 0x3F800000u) badF = 1;
    }
    __syncthreads();
    if (threadIdx.x == 0) g_mask_mode = (badI == 0) ? 1 : ((badF == 0) ? 2 : 0);
}

// ---------------- (1) Compact active (t,w) rows ----------------
__global__ void k_compact(const void* wmask) {
    int r = blockIdx.x * blockDim.x + threadIdx.x;
    if (r < TT * WN && mask_at(wmask, r)) {
        int s = atomicAdd(&g_nact, 1);
        g_act[s] = r;
    }
}

// ---------------- (2) Fused transposes: U,Uw,Ua -> column-major ----------------
__global__ void k_transpose_all(const float* __restrict__ U,
                                const float* __restrict__ Uw,
                                const float* __restrict__ Ua) {
    __shared__ float tile[32][33];
    int z = blockIdx.z;
    const float* in; float* outp; int R, C;
    if (z == 0)      { in = U;  outp = g_Ut;  R = HH; C = H3; }
    else if (z == 1) { in = Uw; outp = g_Uwt; R = HH; C = H3; }
    else             { in = Ua; outp = g_Uat; R = HH; C = HH;
                       if (blockIdx.x >= HH / 32) return; }
    int c0 = blockIdx.x * 32, r0 = blockIdx.y * 32;
    int x = threadIdx.x, y = threadIdx.y;
    #pragma unroll
    for (int i = 0; i < 32; i += 8) tile[y + i][x] = in[(size_t)(r0 + y + i) * C + c0 + x];
    __syncthreads();
    #pragma unroll
    for (int i = 0; i < 32; i += 8) outp[(size_t)(c0 + y + i) * R + r0 + x] = tile[x][y + i];
}

// ---------------- (3) Fused dense GEMMs: pre_x = x@W+b ; pre_a = x@Wa+ba ----
__global__ void k_gemm_fused(const float* __restrict__ A,
                             const float* __restrict__ W,  const float* __restrict__ b,
                             const float* __restrict__ Wa, const float* __restrict__ ba) {
    __shared__ float As[64][33];
    __shared__ float Bs[32][64];
    int bx = blockIdx.x;
    const float* B; const float* bias; float* C; int N, nt;
    if (bx < H3 / 64) { B = W;  bias = b;  C = g_pre_x; N = H3; nt = bx * 64; }
    else              { B = Wa; bias = ba; C = g_pre_a; N = HH; nt = (bx - H3 / 64) * 64; }
    int mt = blockIdx.y * 64;
    int tid = threadIdx.x;
    int tx = tid % 16, ty = tid / 16;
    float acc[4][4] = {};
    for (int k0 = 0; k0 < DD; k0 += 32) {
        #pragma unroll
        for (int p = 0; p < 8; p++) {
            int row = (tid >> 5) + p * 8, kk = tid & 31;
            As[row][kk] = A[(size_t)(mt + row) * DD + k0 + kk];
        }
        #pragma unroll
        for (int p = 0; p < 8; p++) {
            int kk = (tid >> 6) + p * 4, nn = tid & 63;
            Bs[kk][nn] = B[(size_t)(k0 + kk) * N + nt + nn];
        }
        __syncthreads();
        #pragma unroll
        for (int kk = 0; kk < 32; kk++) {
            float a0 = As[ty * 4 + 0][kk], a1 = As[ty * 4 + 1][kk];
            float a2 = As[ty * 4 + 2][kk], a3 = As[ty * 4 + 3][kk];
            float4 b4 = *(const float4*)&Bs[kk][tx * 4];
            acc[0][0] += a0 * b4.x; acc[0][1] += a0 * b4.y; acc[0][2] += a0 * b4.z; acc[0][3] += a0 * b4.w;
            acc[1][0] += a1 * b4.x; acc[1][1] += a1 * b4.y; acc[1][2] += a1 * b4.z; acc[1][3] += a1 * b4.w;
            acc[2][0] += a2 * b4.x; acc[2][1] += a2 * b4.y; acc[2][2] += a2 * b4.z; acc[2][3] += a2 * b4.w;
            acc[3][0] += a3 * b4.x; acc[3][1] += a3 * b4.y; acc[3][2] += a3 * b4.z; acc[3][3] += a3 * b4.w;
        }
        __syncthreads();
    }
    #pragma unroll
    for (int i = 0; i < 4; i++) {
        int row = mt + ty * 4 + i;
        #pragma unroll
        for (int j = 0; j < 4; j++) {
            int col = nt + tx * 4 + j;
            C[(size_t)row * N + col] = acc[i][j] + bias[col];
        }
    }
}

// ---------------- (4) Gathered GEMM: pre_w for active rows ----------------
__global__ void k_gemm_gather(const float* __restrict__ emb, const int* __restrict__ word_ids,
                              const float* __restrict__ B, const float* __restrict__ bias) {
    int nact = g_nact;
    int mt = blockIdx.y * 64;
    if (mt >= nact) return;
    __shared__ int sR[64];
    __shared__ int sWid[64];
    __shared__ float As[64][33];
    __shared__ float Bs[32][64];
    int tid = threadIdx.x;
    if (tid < 64) {
        int ci = mt + tid;
        int r = (ci < nact) ? g_act[ci] : -1;
        sR[tid] = r;
        sWid[tid] = (r >= 0) ? word_ids[r] : 0;
    }
    __syncthreads();
    int tx = tid % 16, ty = tid / 16;
    int nt = blockIdx.x * 64;
    float acc[4][4] = {};
    for (int k0 = 0; k0 < EE; k0 += 32) {
        #pragma unroll
        for (int p = 0; p < 8; p++) {
            int row = (tid >> 5) + p * 8, kk = tid & 31;
            As[row][kk] = emb[(size_t)sWid[row] * EE + k0 + kk];
        }
        #pragma unroll
        for (int p = 0; p < 8; p++) {
            int kk = (tid >> 6) + p * 4, nn = tid & 63;
            Bs[kk][nn] = B[(size_t)(k0 + kk) * H3 + nt + nn];
        }
        __syncthreads();
        #pragma unroll
        for (int kk = 0; kk < 32; kk++) {
            float a0 = As[ty * 4 + 0][kk], a1 = As[ty * 4 + 1][kk];
            float a2 = As[ty * 4 + 2][kk], a3 = As[ty * 4 + 3][kk];
            float4 b4 = *(const float4*)&Bs[kk][tx * 4];
            acc[0][0] += a0 * b4.x; acc[0][1] += a0 * b4.y; acc[0][2] += a0 * b4.z; acc[0][3] += a0 * b4.w;
            acc[1][0] += a1 * b4.x; acc[1][1] += a1 * b4.y; acc[1][2] += a1 * b4.z; acc[1][3] += a1 * b4.w;
            acc[2][0] += a2 * b4.x; acc[2][1] += a2 * b4.y; acc[2][2] += a2 * b4.z; acc[2][3] += a2 * b4.w;
            acc[3][0] += a3 * b4.x; acc[3][1] += a3 * b4.y; acc[3][2] += a3 * b4.z; acc[3][3] += a3 * b4.w;
        }
        __syncthreads();
    }
    #pragma unroll
    for (int i = 0; i < 4; i++) {
        int r = sR[ty * 4 + i];
        if (r >= 0) {
            #pragma unroll
            for (int j = 0; j < 4; j++) {
                int col = nt + tx * 4 + j;
                g_pre_w[(size_t)r * H3 + col] = acc[i][j] + bias[col];
            }
        }
    }
}

// ---------------- (5) Sequential lattice scan ----------------
__global__ void __launch_bounds__(NTH, 1)
k_lattice_seq(const float* __restrict__ h0, const float* __restrict__ c0,
              const int* __restrict__ wstarts, const void* __restrict__ wmask,
              float* __restrict__ out) {
    int tid = threadIdx.x;
    int wid = tid >> 5, lane = tid & 31;
    int hbase = blockIdx.x * HB;

    __shared__ float4 sVec4[1 + WN][HH / 4];   // [0]=h_prev; [1..]=h_s
    __shared__ float4 sCw4[WN][HH / 4];        // full c_w vectors (phase B)
    __shared__ float sDot[128];
    __shared__ float sPreX[3 * HB];
    __shared__ float sPreA[2][HB];
    __shared__ float sPreW[WN][3][HB];
    __shared__ float sCS[WN][HB];
    __shared__ float sIG[HB], sOG[HB], sGG[HB], sCprev[HB];
    __shared__ int sAct[2][WN], sStart[2][WN];
    __shared__ int sNact[2], sNeed[2];

    if (tid < HB) sCprev[tid] = c0[hbase + tid];

    // Prologue for t=0: a word ending at t=0 needs start>=0 with len>=2 -> impossible,
    // so nact(0)==0 by construction.
    if (tid == 0) { sNact[0] = 0; sNeed[0] = 0; }
    if (tid < 3 * HB)
        sPreX[tid] = __ldcg(&g_pre_x[(size_t)(tid / HB) * HH + hbase + (tid % HB)]);
    if (tid >= 32 && tid < 32 + HB)
        sPreA[0][tid - 32] = __ldcg(&g_pre_a[hbase + (tid - 32)]);
    __syncthreads();

    unsigned int pno = 0;

    // Prefetch next step's non-recurrent data (runs while tid0 spins at a barrier).
    // Caller guarantees tid >= 32.
    auto do_prefetch = [&](int tn, int m) {
        int n2 = sNact[m], need2 = sNeed[m];
        if (tid < 32 + 3 * HB) {                       // 32..55 : pre_x
            int s = tid - 32;
            sPreX[s] = __ldcg(&g_pre_x[(size_t)tn * H3 + (s / HB) * HH + hbase + (s % HB)]);
        } else if (tid < 56 + HB) {                    // 56..63 : pre_a
            sPreA[m][tid - 56] = __ldcg(&g_pre_a[(size_t)tn * HH + hbase + (tid - 56)]);
        } else if (tid < 64 + WN * 3 * HB) {           // 64..159 : pre_w
            int q = tid - 64;
            if (q < n2 * 3 * HB) {
                int a = q / (3 * HB), s = q % (3 * HB);
                sPreW[a][s / HB][s % HB] =
                    __ldcg(&g_pre_w[(size_t)(tn * WN + sAct[m][a]) * H3 +
                                    (s / HB) * HH + hbase + (s % HB)]);
            }
        } else if (tid < 160 + WN * HB) {              // 160..191 : c_s (ready rows)
            int q = tid - 160;
            if (q < n2 * HB) {
                int a = q / HB, hh = q % HB;
                if (!((need2 >> a) & 1))
                    sCS[a][hh] = __ldcg(out + (size_t)sStart[m][a] * (2 * HH) + HH + hbase + hh);
            }
        }
        if (tid >= 192) {                              // 192..511 : h_s vectors (ready rows)
            for (int i = tid - 192; i < n2 * 128; i += NTH - 192) {
                int a = i >> 7, j = i & 127;
                if (!((need2 >> a) & 1))
                    sVec4[1 + a][j] =
                        __ldcg((const float4*)(out + (size_t)sStart[m][a] * (2 * HH)) + j);
            }
        }
    };

    for (int t = 0; t < TT; t++) {
        int p = t & 1;
        int nact = sNact[p], need = sNeed[p];

        // ---- top staging: h_prev + any words whose source row is t-1 ----
        {
            const float4* hp = (t == 0) ? (const float4*)h0
                                        : (const float4*)(out + (size_t)(t - 1) * (2 * HH));
            if (tid < 128) sVec4[0][tid] = __ldcg(hp + tid);
            for (int a = 0; a < nact; a++) {
                if ((need >> a) & 1) {
                    int st = sStart[p][a];
                    if (tid >= 128 && tid < 256)
                        sVec4[1 + a][tid - 128] =
                            __ldcg((const float4*)(out + (size_t)st * (2 * HH)) + (tid - 128));
                    if (tid >= 256 && tid < 256 + HB)
                        sCS[a][tid - 256] = __ldcg(out + (size_t)st * (2 * HH) + HH + hbase + (tid - 256));
                }
            }
        }
        __syncthreads();

        // ---- phase A dots (warps 0..NW-2) ; metadata for t+1 (warp NW-1) ----
        int ndots = 3 * HB * (1 + nact);
        if (wid < NW - 1) {
            for (int d = wid; d < ndots; d += NW - 1) {
                int grp = d / (3 * HB), s = d % (3 * HB);
                const float4* vec = sVec4[grp];
                const float* wt = (grp == 0) ? g_Ut : g_Uwt;
                const float4* col = (const float4*)(wt + (size_t)((s / HB) * HH + hbase + (s % HB)) * HH);
                float acc = 0.f;
                #pragma unroll
                for (int i = 0; i < 4; i++) {
                    float4 v = vec[lane + 32 * i];
                    float4 c = __ldg(col + lane + 32 * i);
                    acc += v.x * c.x + v.y * c.y + v.z * c.z + v.w * c.w;
                }
                #pragma unroll
                for (int o = 16; o; o >>= 1) acc += __shfl_down_sync(0xffffffffu, acc, o);
                if (lane == 0) sDot[d] = acc;
            }
        } else if (lane == 0 && t + 1 < TT) {
            int m = p ^ 1, n = 0, nd = 0;
            #pragma unroll
            for (int w = 0; w < WN; w++) {
                int r = (t + 1) * WN + w;
                if (mask_at(wmask, r)) {
                    sAct[m][n] = w;
                    int st = wstarts[r];
                    sStart[m][n] = st;
                    if (st == t) nd |= 1 << n;   // source row not yet published
                    n++;
                }
            }
            sNact[m] = n; sNeed[m] = nd;
        }
        __syncthreads();

        // ---- phase A pointwise ----
        if (tid < HB) {
            sIG[tid] = sigm(sPreX[tid] + sDot[tid]);
            sOG[tid] = sigm(sPreX[HB + tid] + sDot[HB + tid]);
            sGG[tid] = tanh_fast(sPreX[2 * HB + tid] + sDot[2 * HB + tid]);
        }
        {
            int q = tid - 32;
            if (q >= 0 && q < nact * HB) {
                int a = q / HB, hh = q % HB, base = (1 + a) * 3 * HB;
                float f  = sPreW[a][0][hh] + sDot[base + hh];
                float iw = sPreW[a][1][hh] + sDot[base + HB + hh];
                float gw = sPreW[a][2][hh] + sDot[base + 2 * HB + hh];
                float cw = sigm(f) * sCS[a][hh] + sigm(iw) * tanh_fast(gw);
                __stcg(&g_cw[sAct[p][a] * HH + hbase + hh], cw);
            }
        }

        if (nact > 0) {
            // ---- grid barrier 1 (publish c_w) ; prefetch t+1 during spin ----
            __syncthreads();
            pno++;
            if (tid == 0) {
                arrive_release(&g_ctr);
                unsigned int tgt = pno * NB;
                while (ld_acq(&g_ctr) < tgt) {}
            } else if (tid >= 32 && t + 1 < TT) {
                do_prefetch(t + 1, p ^ 1);
            }
            __syncthreads();

            // ---- stage full c_w vectors ----
            for (int i = tid; i < nact * 128; i += NTH) {
                int a = i >> 7, j = i & 127;
                sCw4[a][j] = __ldcg((const float4*)(g_cw + sAct[p][a] * HH) + j);
            }
            __syncthreads();

            // ---- phase B dots: c_w @ Ua cols ----
            for (int d = wid; d < nact * HB; d += NW) {
                int a = d / HB, hh = d % HB;
                const float4* vec = sCw4[a];
                const float4* col = (const float4*)(g_Uat + (size_t)(hbase + hh) * HH);
                float acc = 0.f;
                #pragma unroll
                for (int i = 0; i < 4; i++) {
                    float4 v = vec[lane + 32 * i];
                    float4 c = __ldg(col + lane + 32 * i);
                    acc += v.x * c.x + v.y * c.y + v.z * c.z + v.w * c.w;
                }
                #pragma unroll
                for (int o = 16; o; o >>= 1) acc += __shfl_down_sync(0xffffffffu, acc, o);
                if (lane == 0) sDot[d] = acc;
            }
            __syncthreads();
        }

        // ---- phase B pointwise: combine + write h,c ----
        if (tid < HB) {
            int hh = tid;
            float c1;
            if (nact > 0) {
                float e0 = __expf(sIG[hh]);
                float num = e0 * sGG[hh], den = e0;
                for (int a = 0; a < nact; a++) {
                    float al = sigm(sPreA[p][hh] + sDot[a * HB + hh]);
                    float ea = __expf(al);
                    float cwv = ((const float*)sCw4[a])[hbase + hh];
                    num += ea * cwv;
                    den += ea;
                }
                c1 = num / den;
            } else {
                c1 = (1.0f - sIG[hh]) * sCprev[hh] + sIG[hh] * sGG[hh];
            }
            float h1 = sOG[hh] * tanh_fast(c1);
            __stcg(out + (size_t)t * (2 * HH) + hbase + hh, h1);
            __stcg(out + (size_t)t * (2 * HH) + HH + hbase + hh, c1);
            sCprev[hh] = c1;
        }
        if (t == TT - 1) break;

        // ---- grid barrier 2 (publish h1,c1) ; prefetch if barrier 1 skipped ----
        __syncthreads();
        pno++;
        if (tid == 0) {
            arrive_release(&g_ctr);
            unsigned int tgt = pno * NB;
            while (ld_acq(&g_ctr) < tgt) {}
        } else if (tid >= 32 && nact == 0) {
            do_prefetch(t + 1, p ^ 1);
        }
        __syncthreads();
    }
}

// ---------------- Launch ----------------
extern "C" void kernel_launch(void* const* d_in, const int* in_sizes, int n_in,
                              void* d_out, int out_size) {
    const float* x       = (const float*)d_in[0];
    const int*   wids    = (const int*)d_in[1];
    const int*   wstarts = (const int*)d_in[2];
    const void*  wmask   = (const void*)d_in[3];
    const float* h0      = (const float*)d_in[4];
    const float* c0      = (const float*)d_in[5];
    const float* emb     = (const float*)d_in[6];
    const float* W       = (const float*)d_in[7];
    const float* U       = (const float*)d_in[8];
    const float* b       = (const float*)d_in[9];
    const float* Wa      = (const float*)d_in[10];
    const float* Ua      = (const float*)d_in[11];
    const float* ba      = (const float*)d_in[12];
    const float* Ww      = (const float*)d_in[13];
    const float* Uw      = (const float*)d_in[14];
    const float* bw      = (const float*)d_in[15];
    float* out = (float*)d_out;

    // launch index:                                           0
    k_init<<<1, 256>>>((const unsigned int*)wmask);
    //                                                         1
    k_compact<<<(TT * WN + 255) / 256, 256>>>(wmask);
    //                                                         2
    k_transpose_all<<<dim3(H3 / 32, HH / 32, 3), dim3(32, 8)>>>(U, Uw, Ua);
    //                                                         3
    k_gemm_fused<<<dim3(H3 / 64 + HH / 64, TT / 64), 256>>>(x, W, b, Wa, ba);
    //                                                         4
    k_gemm_gather<<<dim3(H3 / 64, (TT * WN) / 64), 256>>>(emb, wids, Ww, bw);
    //                                                         5  <- ncu -s 5 profiles this
    k_lattice_seq<<<NB, NTH>>>(h0, c0, wstarts, wmask, out);
}